// round 9
// baseline (speedup 1.0000x reference)
#include <cuda_runtime.h>
#include <cuda_bf16.h>
#include <cstdint>

// LinearAttention: out[n,l,h,e] = (phi(Q)@KV) * Z, phi = elu+1 (vlen cancels)
//   KV = sum_s phi(K)[s,d] * V[s,e] ;  Z = 1/(phi(Q).Ksum + 1e-6)
//
// R9: occupancy push (both phases were ~45% DRAM, nothing saturated, 2 CTA/SM).
//  p1: no k-split (warp = 2m x 2g, accs 16 regs), scratch aliased -> 73.7KB
//      smem, launch_bounds(256,3); single partial slot (reduce traffic halved).
//  p2: 1 l-tile/CTA (2048 CTAs), Z scalar-side (B = 64 rows), warp = 2m x 4g,
//      smem 55.8KB, launch_bounds(256,3). B consumed [d][e] via ldm2t.trans.

#define DEV_INLINE __device__ __forceinline__

constexpr int Hh = 8, Dd = 64, Ll = 8192, Ss = 8192, Nn = 4;
constexpr int NH = Nn * Hh;                // 32
constexpr int ROWSTRIDE = Hh * Dd;         // 512
constexpr int P1_CHUNKS = 32;
constexpr int P1_SCHUNK = Ss / P1_CHUNKS;  // 256 s per CTA (4 tiles of 64)

__device__ __align__(16) float g_part_kv[(size_t)P1_CHUNKS * NH * 4096];
__device__ __align__(16) float g_part_ks[P1_CHUNKS * NH * 64];
__device__ __align__(16) float g_kv[NH * 4096];   // [nh][d][e]
__device__ __align__(16) float g_ks[NH * 64];

using u64 = unsigned long long;

DEV_INLINE float featmap(float x) { return __expf(fminf(x, 0.f)) + fmaxf(x, 0.f); }
DEV_INLINE unsigned bf2u(__nv_bfloat162 v) { return *reinterpret_cast<unsigned*>(&v); }
DEV_INLINE void bsplit2(float a, float b, unsigned& h, unsigned& l) {
    __nv_bfloat162 hv = __floats2bfloat162_rn(a, b);
    float2 hf = __bfloat1622float2(hv);
    __nv_bfloat162 lv = __floats2bfloat162_rn(a - hf.x, b - hf.y);
    h = bf2u(hv); l = bf2u(lv);
}
DEV_INLINE uint32_t smem_u32(const void* p) {
    uint32_t a;
    asm("{ .reg .u64 t; cvta.to.shared.u64 t, %1; cvt.u32.u64 %0, t; }"
        : "=r"(a) : "l"(p));
    return a;
}
DEV_INLINE void mma_bf16(float4& c, const uint32_t a[4], uint32_t b0, uint32_t b1) {
    asm volatile(
        "mma.sync.aligned.m16n8k16.row.col.f32.bf16.bf16.f32 "
        "{%0,%1,%2,%3}, {%4,%5,%6,%7}, {%8,%9}, {%0,%1,%2,%3};"
        : "+f"(c.x), "+f"(c.y), "+f"(c.z), "+f"(c.w)
        : "r"(a[0]), "r"(a[1]), "r"(a[2]), "r"(a[3]), "r"(b0), "r"(b1));
}
DEV_INLINE void ldm4t(uint32_t* r, uint32_t addr) {
    asm volatile(
        "ldmatrix.sync.aligned.m8n8.x4.trans.shared.b16 {%0,%1,%2,%3}, [%4];"
        : "=r"(r[0]), "=r"(r[1]), "=r"(r[2]), "=r"(r[3]) : "r"(addr));
}
DEV_INLINE void ldm2t(uint32_t* r, uint32_t addr) {
    asm volatile(
        "ldmatrix.sync.aligned.m8n8.x2.trans.shared.b16 {%0,%1}, [%2];"
        : "=r"(r[0]), "=r"(r[1]) : "r"(addr));
}

// ---- p1 smem: 4 arrays [2buf][64 rows][144B]; ksum scratch aliases buf0 KH ----
constexpr uint32_t P1_KH = 0;
constexpr uint32_t P1_KL = 18432;
constexpr uint32_t P1_VH = 36864;
constexpr uint32_t P1_VL = 55296;
constexpr uint32_t P1_DSM = 73728;

// ============================================================================
// Phase 1: D[d][e] = phiK^T @ V. 256 thr / 8 warps, warp = 2 m-tiles x 2
// e-groups, all 4 kt. mi = wid>>2, ni = wid&3. Grid (P1_CHUNKS, NH).
// ============================================================================
__global__ __launch_bounds__(256, 3) void p1_kernel(const float* __restrict__ keys,
                                                    const float* __restrict__ values) {
    extern __shared__ __align__(16) char sm1[];

    const int t   = threadIdx.x;
    const int wid = t >> 5, lid = t & 31;
    const int grp = lid >> 3, r8 = lid & 7;
    const int qg  = lid >> 2, tg = lid & 3;
    const int nh  = blockIdx.y;
    const int n   = nh >> 3, h = nh & 7;
    const int s0  = blockIdx.x * P1_SCHUNK;
    const int mi  = wid >> 2, ni = wid & 3;

    const uint32_t smb = smem_u32(sm1);
    // A (phiK^T, m=d cols / k=s rows), ldm4t (validated R8)
    const uint32_t aoff = (uint32_t)((r8 + ((grp & 2) ? 8 : 0)) * 144 +
                                     ((grp & 1) ? 8 : 0) * 2);
    // B (V, k=s rows / n=e cols), ldm2t (validated R8)
    const uint32_t boff = (uint32_t)((r8 + ((grp & 1) ? 8 : 0)) * 144);

    float4 acc[2][2];
#pragma unroll
    for (int i = 0; i < 2; i++)
#pragma unroll
        for (int j = 0; j < 2; j++) acc[i][j] = make_float4(0.f, 0.f, 0.f, 0.f);
    float4 ksum4 = make_float4(0.f, 0.f, 0.f, 0.f);

    const int c4 = t & 15, rbase = t >> 4;

    float4 bk[4], bv[4];
#pragma unroll
    for (int j = 0; j < 4; ++j) {
        size_t row = (size_t)(n * Ss + s0 + rbase + 16 * j);
        bk[j] = *(const float4*)(keys   + row * ROWSTRIDE + h * Dd + c4 * 4);
        bv[j] = *(const float4*)(values + row * ROWSTRIDE + h * Dd + c4 * 4);
    }

    for (int tile = 0; tile < 4; ++tile) {
        const int b = tile & 1;
        char* KH = sm1 + P1_KH + b * 9216;
        char* KL = sm1 + P1_KL + b * 9216;
        char* VH = sm1 + P1_VH + b * 9216;
        char* VL = sm1 + P1_VL + b * 9216;
#pragma unroll
        for (int j = 0; j < 4; ++j) {
            const int sr = rbase + 16 * j;
            unsigned h0, l0_, h1, l1;
            float fx = featmap(bk[j].x), fy = featmap(bk[j].y);
            float fz = featmap(bk[j].z), fw = featmap(bk[j].w);
            ksum4.x += fx; ksum4.y += fy; ksum4.z += fz; ksum4.w += fw;
            bsplit2(fx, fy, h0, l0_);
            bsplit2(fz, fw, h1, l1);
            *(u64*)(KH + sr * 144 + c4 * 8) = ((u64)h1 << 32) | h0;
            *(u64*)(KL + sr * 144 + c4 * 8) = ((u64)l1 << 32) | l0_;
            bsplit2(bv[j].x, bv[j].y, h0, l0_);
            bsplit2(bv[j].z, bv[j].w, h1, l1);
            *(u64*)(VH + sr * 144 + c4 * 8) = ((u64)h1 << 32) | h0;
            *(u64*)(VL + sr * 144 + c4 * 8) = ((u64)l1 << 32) | l0_;
        }
        __syncthreads();

        if (tile + 1 < 4) {
#pragma unroll
            for (int j = 0; j < 4; ++j) {
                size_t row = (size_t)(n * Ss + s0 + (tile + 1) * 64 + rbase + 16 * j);
                bk[j] = *(const float4*)(keys   + row * ROWSTRIDE + h * Dd + c4 * 4);
                bv[j] = *(const float4*)(values + row * ROWSTRIDE + h * Dd + c4 * 4);
            }
        }

        const uint32_t KHu = smb + P1_KH + b * 9216;
        const uint32_t KLu = smb + P1_KL + b * 9216;
        const uint32_t VHu = smb + P1_VH + b * 9216;
        const uint32_t VLu = smb + P1_VL + b * 9216;
#pragma unroll
        for (int kt = 0; kt < 4; ++kt) {
            uint32_t ah[2][4], al[2][4];
#pragma unroll
            for (int m2 = 0; m2 < 2; ++m2) {
                const int mt = mi * 2 + m2;
                ldm4t(ah[m2], KHu + (uint32_t)(kt * 16 * 144 + mt * 32) + aoff);
                ldm4t(al[m2], KLu + (uint32_t)(kt * 16 * 144 + mt * 32) + aoff);
            }
#pragma unroll
            for (int g2 = 0; g2 < 2; ++g2) {
                const int gx = ni * 2 + g2;
                uint32_t bh[2], bl[2];
                ldm2t(bh, VHu + (uint32_t)(kt * 16 * 144 + gx * 16) + boff);
                ldm2t(bl, VLu + (uint32_t)(kt * 16 * 144 + gx * 16) + boff);
#pragma unroll
                for (int m2 = 0; m2 < 2; ++m2) {
                    mma_bf16(acc[m2][g2], ah[m2], bh[0], bh[1]);
                    mma_bf16(acc[m2][g2], ah[m2], bl[0], bl[1]);
                    mma_bf16(acc[m2][g2], al[m2], bh[0], bh[1]);
                }
            }
        }
        // next store targets the other buffer; next-iteration sync protects reuse
    }

    // Ksum tree via scratch aliased onto buf0 KH (idle after final sync)
    __syncthreads();
    float* scr = (float*)(sm1 + P1_KH);
    *(float4*)(scr + rbase * 68 + c4 * 4) = ksum4;
    __syncthreads();
    if (t < 64) {
        float s = 0.f;
#pragma unroll
        for (int r = 0; r < 16; ++r) s += scr[r * 68 + t];
        g_part_ks[(blockIdx.x * NH + nh) * 64 + t] = s;
    }

    // writeback partial [d][e], single slot per chunk
    float* base = g_part_kv + ((size_t)blockIdx.x * NH + nh) * 4096;
#pragma unroll
    for (int m2 = 0; m2 < 2; ++m2)
#pragma unroll
        for (int g2 = 0; g2 < 2; ++g2) {
            const int d0 = (mi * 2 + m2) * 16 + qg;
            const int e0 = (ni * 2 + g2) * 8 + tg * 2;
            *(float2*)(base + d0 * 64 + e0)       = make_float2(acc[m2][g2].x, acc[m2][g2].y);
            *(float2*)(base + (d0 + 8) * 64 + e0) = make_float2(acc[m2][g2].z, acc[m2][g2].w);
        }
}

// ============================================================================
// Phase 1b: fixed-order reduction (32 slots)
// ============================================================================
__global__ void reduce_kernel() {
    int i = blockIdx.x * 256 + threadIdx.x;
    if (i < NH * 1024) {
        float4 s = make_float4(0.f, 0.f, 0.f, 0.f);
#pragma unroll
        for (int c = 0; c < P1_CHUNKS; c++) {
            float4 p = *(const float4*)(g_part_kv + (size_t)c * NH * 4096 + i * 4);
            s.x += p.x; s.y += p.y; s.z += p.z; s.w += p.w;
        }
        *(float4*)(g_kv + i * 4) = s;
    } else if (i < NH * 1024 + NH * 16) {
        int j = i - NH * 1024;
        float4 s = make_float4(0.f, 0.f, 0.f, 0.f);
#pragma unroll
        for (int c = 0; c < P1_CHUNKS; c++) {
            float4 p = *(const float4*)(g_part_ks + c * NH * 64 + j * 4);
            s.x += p.x; s.y += p.y; s.z += p.z; s.w += p.w;
        }
        *(float4*)(g_ks + j * 4) = s;
    }
}

// ---- p2 smem: single Q buffer + B(64 rows) + z scratch ----
constexpr uint32_t P2_QH = 0;           // 128x144
constexpr uint32_t P2_QL = 18432;
constexpr uint32_t P2_BH = 36864;       // 64x144
constexpr uint32_t P2_BL = 46080;
constexpr uint32_t P2_ZS = 55296;       // 128 floats
constexpr uint32_t P2_DSM = 55808;

// ============================================================================
// Phase 2: out = (phiQ @ KV) * Z. 256 thr / 8 warps: warp = 2 m-tiles x 4
// e-groups (mi = wid>>1, ni = wid&1). 1 l-tile (128 l) per CTA.
// Z scalar-side (shfl tree during staging). Grid (Ll/128, NH).
// ============================================================================
__global__ __launch_bounds__(256, 3) void p2_kernel(const float* __restrict__ queries,
                                                    float* __restrict__ out) {
    extern __shared__ __align__(16) char sm2[];
    char* QH = sm2 + P2_QH; char* QL = sm2 + P2_QL;
    char* BH = sm2 + P2_BH; char* BL = sm2 + P2_BL;
    float* zst = (float*)(sm2 + P2_ZS);

    const int t    = threadIdx.x;
    const int wid  = t >> 5, lane = t & 31;
    const int grp  = lane >> 3, r8 = lane & 7;
    const int qg   = lane >> 2, tg = lane & 3;
    const int nh   = blockIdx.y;
    const int n    = nh >> 3, h = nh & 7;
    const int lbase = blockIdx.x * 128;
    const int mi   = wid >> 1, ni = wid & 1;

    const uint32_t smb = smem_u32(sm2);
    const uint32_t boffB = (uint32_t)((r8 + ((grp & 1) ? 8 : 0)) * 144);

    // stage B = KV[d][e] (row = d = k)
    if (t < 64) {
        const float* src = g_kv + (size_t)nh * 4096 + t * 64;
#pragma unroll
        for (int c = 0; c < 16; ++c) {
            float4 v = *(const float4*)(src + c * 4);
            unsigned hxy, lxy, hzw, lzw;
            bsplit2(v.x, v.y, hxy, lxy);
            bsplit2(v.z, v.w, hzw, lzw);
            *(u64*)(BH + t * 144 + c * 8) = ((u64)hzw << 32) | hxy;
            *(u64*)(BL + t * 144 + c * 8) = ((u64)lzw << 32) | lxy;
        }
    }

    const int c4 = t & 15, rbase = t >> 4;
    const float4 ks4 = *(const float4*)(g_ks + nh * 64 + c4 * 4);

    // stage Q (phi + split) + Z partial dots
    const float* qbase = queries + ((size_t)(n * Ll + lbase) * ROWSTRIDE + h * Dd);
#pragma unroll
    for (int k2 = 0; k2 < 8; ++k2) {
        const int lr = rbase + 16 * k2;
        float4 qv = *(const float4*)(qbase + (size_t)lr * ROWSTRIDE + c4 * 4);
        unsigned hxy, lxy, hzw, lzw;
        float fx = featmap(qv.x), fy = featmap(qv.y);
        float fz = featmap(qv.z), fw = featmap(qv.w);
        float pz = fx * ks4.x + fy * ks4.y + fz * ks4.z + fw * ks4.w;
        pz += __shfl_xor_sync(0xFFFFFFFFu, pz, 1);
        pz += __shfl_xor_sync(0xFFFFFFFFu, pz, 2);
        pz += __shfl_xor_sync(0xFFFFFFFFu, pz, 4);
        pz += __shfl_xor_sync(0xFFFFFFFFu, pz, 8);
        if (c4 == 0) zst[lr] = pz;
        bsplit2(fx, fy, hxy, lxy);
        bsplit2(fz, fw, hzw, lzw);
        *(u64*)(QH + lr * 144 + c4 * 8) = ((u64)hzw << 32) | hxy;
        *(u64*)(QL + lr * 144 + c4 * 8) = ((u64)lzw << 32) | lxy;
    }
    __syncthreads();

    float4 C[2][4];
#pragma unroll
    for (int m2 = 0; m2 < 2; ++m2)
#pragma unroll
        for (int gi = 0; gi < 4; ++gi) C[m2][gi] = make_float4(0.f, 0.f, 0.f, 0.f);

    const uint32_t BHu = smb + P2_BH, BLu = smb + P2_BL;
#pragma unroll
    for (int kt = 0; kt < 4; ++kt) {
        const int kb = kt * 32 + tg * 4;
        uint32_t ah[2][4], al[2][4];
#pragma unroll
        for (int m2 = 0; m2 < 2; ++m2) {
            const int r0 = (mi * 2 + m2) * 16 + qg;
            ah[m2][0] = *(const uint32_t*)(QH + r0 * 144 + kb);
            ah[m2][1] = *(const uint32_t*)(QH + (r0 + 8) * 144 + kb);
            ah[m2][2] = *(const uint32_t*)(QH + r0 * 144 + kb + 16);
            ah[m2][3] = *(const uint32_t*)(QH + (r0 + 8) * 144 + kb + 16);
            al[m2][0] = *(const uint32_t*)(QL + r0 * 144 + kb);
            al[m2][1] = *(const uint32_t*)(QL + (r0 + 8) * 144 + kb);
            al[m2][2] = *(const uint32_t*)(QL + r0 * 144 + kb + 16);
            al[m2][3] = *(const uint32_t*)(QL + (r0 + 8) * 144 + kb + 16);
        }
#pragma unroll
        for (int gi = 0; gi < 4; ++gi) {
            const int gx = ni * 4 + gi;
            uint32_t bh[2], bl[2];
            ldm2t(bh, BHu + (uint32_t)(kt * 16 * 144 + gx * 16) + boffB);
            ldm2t(bl, BLu + (uint32_t)(kt * 16 * 144 + gx * 16) + boffB);
#pragma unroll
            for (int m2 = 0; m2 < 2; ++m2) {
                mma_bf16(C[m2][gi], ah[m2], bh[0], bh[1]);
                mma_bf16(C[m2][gi], ah[m2], bl[0], bl[1]);
                mma_bf16(C[m2][gi], al[m2], bh[0], bh[1]);
            }
        }
    }

    // epilogue
#pragma unroll
    for (int m2 = 0; m2 < 2; ++m2) {
        const int rl = (mi * 2 + m2) * 16 + qg;
        float i0 = 1.0f / (zst[rl] + 1e-6f);
        float i1 = 1.0f / (zst[rl + 8] + 1e-6f);
        const int row = lbase + rl;
        float* p0 = out + ((size_t)(n * Ll + row) * Hh + h) * Dd;
        float* p1 = p0 + (size_t)8 * ROWSTRIDE;
#pragma unroll
        for (int gi = 0; gi < 4; ++gi) {
            const int col = (ni * 4 + gi) * 8 + tg * 2;
            *(float2*)(p0 + col) = make_float2(C[m2][gi].x * i0, C[m2][gi].y * i0);
            *(float2*)(p1 + col) = make_float2(C[m2][gi].z * i1, C[m2][gi].w * i1);
        }
    }
}

// ============================================================================
extern "C" void kernel_launch(void* const* d_in, const int* in_sizes, int n_in,
                              void* d_out, int out_size) {
    const float* q = (const float*)d_in[0];
    const float* k = (const float*)d_in[1];
    const float* v = (const float*)d_in[2];
    float* o = (float*)d_out;
    (void)in_sizes; (void)n_in; (void)out_size;

    cudaFuncSetAttribute(p1_kernel, cudaFuncAttributeMaxDynamicSharedMemorySize, P1_DSM);
    cudaFuncSetAttribute(p2_kernel, cudaFuncAttributeMaxDynamicSharedMemorySize, P2_DSM);

    p1_kernel<<<dim3(P1_CHUNKS, NH), 256, P1_DSM>>>(k, v);
    reduce_kernel<<<(NH * 1024 + NH * 16 + 255) / 256, 256>>>();
    p2_kernel<<<dim3(Ll / 128, NH), 256, P2_DSM>>>(q, o);
}

// round 11
// speedup vs baseline: 1.1812x; 1.1812x over previous
#include <cuda_runtime.h>
#include <cuda_bf16.h>
#include <cstdint>

// LinearAttention: out[n,l,h,e] = (phi(Q)@KV) * Z, phi = elu+1 (vlen cancels)
//   KV = sum_s phi(K)[s,d] * V[s,e] ;  Z = 1/(phi(Q).Ksum + 1e-6)
//
// R11 = R10 with the d-coverage bug fixed: p1 warp cells restored to
// 2 m-tiles x 4 d-groups (gx = ni*4+g2 covers all 8 d-groups; R10's 2x2
// left d=32..63 uncomputed -> rel_err 0.5).
//  p1: D[e][d] = V^T @ phiK, warp grid mi2 x ni2 x ki2 (R8-measured shape),
//      k-split pairs combined in-CTA (16KB scratch on dead K buffers),
//      Ksum scalar-side (scratch on dead V buffer). 32 partial slots.
//  p2: R7 skeleton (2 l-tiles/CTA, Q double-buffered, warp = m16 tile,
//      direct-LDS fragments) + scalar-side Z; B = KV[e][d] 64 rows.

#define DEV_INLINE __device__ __forceinline__

constexpr int Hh = 8, Dd = 64, Ll = 8192, Ss = 8192, Nn = 4;
constexpr int NH = Nn * Hh;                // 32
constexpr int ROWSTRIDE = Hh * Dd;         // 512
constexpr int P1_CHUNKS = 32;
constexpr int P1_SCHUNK = Ss / P1_CHUNKS;  // 256 s per CTA (4 tiles of 64)

__device__ __align__(16) float g_part_kv[(size_t)P1_CHUNKS * NH * 4096]; // [e][d]
__device__ __align__(16) float g_part_ks[P1_CHUNKS * NH * 64];
__device__ __align__(16) float g_kv[NH * 4096];   // [nh][e][d]
__device__ __align__(16) float g_ks[NH * 64];

using u64 = unsigned long long;

DEV_INLINE float featmap(float x) { return __expf(fminf(x, 0.f)) + fmaxf(x, 0.f); }
DEV_INLINE unsigned bf2u(__nv_bfloat162 v) { return *reinterpret_cast<unsigned*>(&v); }
DEV_INLINE void bsplit2(float a, float b, unsigned& h, unsigned& l) {
    __nv_bfloat162 hv = __floats2bfloat162_rn(a, b);
    float2 hf = __bfloat1622float2(hv);
    __nv_bfloat162 lv = __floats2bfloat162_rn(a - hf.x, b - hf.y);
    h = bf2u(hv); l = bf2u(lv);
}
DEV_INLINE uint32_t smem_u32(const void* p) {
    uint32_t a;
    asm("{ .reg .u64 t; cvta.to.shared.u64 t, %1; cvt.u32.u64 %0, t; }"
        : "=r"(a) : "l"(p));
    return a;
}
DEV_INLINE void mma_bf16(float4& c, const uint32_t a[4], uint32_t b0, uint32_t b1) {
    asm volatile(
        "mma.sync.aligned.m16n8k16.row.col.f32.bf16.bf16.f32 "
        "{%0,%1,%2,%3}, {%4,%5,%6,%7}, {%8,%9}, {%0,%1,%2,%3};"
        : "+f"(c.x), "+f"(c.y), "+f"(c.z), "+f"(c.w)
        : "r"(a[0]), "r"(a[1]), "r"(a[2]), "r"(a[3]), "r"(b0), "r"(b1));
}
DEV_INLINE void ldm4t(uint32_t* r, uint32_t addr) {
    asm volatile(
        "ldmatrix.sync.aligned.m8n8.x4.trans.shared.b16 {%0,%1,%2,%3}, [%4];"
        : "=r"(r[0]), "=r"(r[1]), "=r"(r[2]), "=r"(r[3]) : "r"(addr));
}
DEV_INLINE void ldm2t(uint32_t* r, uint32_t addr) {
    asm volatile(
        "ldmatrix.sync.aligned.m8n8.x2.trans.shared.b16 {%0,%1}, [%2];"
        : "=r"(r[0]), "=r"(r[1]) : "r"(addr));
}

// ---- p1 smem: K/V hi/lo, each 2buf x 64 x 144B ----
// combine scratch (16KB) aliases KH[0..16384); ksum scratch aliases VH buf0.
constexpr uint32_t P1_KH = 0;
constexpr uint32_t P1_KL = 18432;
constexpr uint32_t P1_VH = 36864;
constexpr uint32_t P1_VL = 55296;
constexpr uint32_t P1_DSM = 73728;

// ============================================================================
// Phase 1: D[e][d] = V^T @ phiK. 256 thr / 8 warps.
// wid: ki=wid&1 (kt pair), ni=(wid>>1)&1 (d-group quad), mi=wid>>2 (e-tiles).
// Warp cells: 2 m-tiles x 4 d-groups (gx = ni*4+g2 -> all 64 d).
// k-split pairs combined in-CTA via smem. Grid (P1_CHUNKS, NH).
// ============================================================================
__global__ __launch_bounds__(256) void p1_kernel(const float* __restrict__ keys,
                                                 const float* __restrict__ values) {
    extern __shared__ __align__(16) char sm1[];

    const int t   = threadIdx.x;
    const int wid = t >> 5, lid = t & 31;
    const int grp = lid >> 3, r8 = lid & 7;
    const int qg  = lid >> 2, tg = lid & 3;
    const int nh  = blockIdx.y;
    const int n   = nh >> 3, h = nh & 7;
    const int s0  = blockIdx.x * P1_SCHUNK;
    const int ki  = wid & 1, ni = (wid >> 1) & 1, mi = wid >> 2;

    const uint32_t smb = smem_u32(sm1);
    // A = V (m=e cols / k=s rows), ldm4t (validated R6/R7)
    const uint32_t aoff = (uint32_t)((r8 + ((grp & 2) ? 8 : 0)) * 144 +
                                     ((grp & 1) ? 8 : 0) * 2);
    // B = phiK (k=s rows / n=d cols), ldm2t (validated R8)
    const uint32_t boff = (uint32_t)((r8 + ((grp & 1) ? 8 : 0)) * 144);

    float4 acc[2][4];
#pragma unroll
    for (int i = 0; i < 2; i++)
#pragma unroll
        for (int j = 0; j < 4; j++) acc[i][j] = make_float4(0.f, 0.f, 0.f, 0.f);
    float4 ksum4 = make_float4(0.f, 0.f, 0.f, 0.f);

    const int c4 = t & 15, rbase = t >> 4;

    float4 bk[4], bv[4];
#pragma unroll
    for (int j = 0; j < 4; ++j) {
        size_t row = (size_t)(n * Ss + s0 + rbase + 16 * j);
        bk[j] = *(const float4*)(keys   + row * ROWSTRIDE + h * Dd + c4 * 4);
        bv[j] = *(const float4*)(values + row * ROWSTRIDE + h * Dd + c4 * 4);
    }

    for (int tile = 0; tile < 4; ++tile) {
        const int b = tile & 1;
        char* KH = sm1 + P1_KH + b * 9216;
        char* KL = sm1 + P1_KL + b * 9216;
        char* VH = sm1 + P1_VH + b * 9216;
        char* VL = sm1 + P1_VL + b * 9216;
#pragma unroll
        for (int j = 0; j < 4; ++j) {
            const int sr = rbase + 16 * j;
            unsigned h0, l0_, h1, l1;
            float fx = featmap(bk[j].x), fy = featmap(bk[j].y);
            float fz = featmap(bk[j].z), fw = featmap(bk[j].w);
            ksum4.x += fx; ksum4.y += fy; ksum4.z += fz; ksum4.w += fw;
            bsplit2(fx, fy, h0, l0_);
            bsplit2(fz, fw, h1, l1);
            *(u64*)(KH + sr * 144 + c4 * 8) = ((u64)h1 << 32) | h0;
            *(u64*)(KL + sr * 144 + c4 * 8) = ((u64)l1 << 32) | l0_;
            bsplit2(bv[j].x, bv[j].y, h0, l0_);
            bsplit2(bv[j].z, bv[j].w, h1, l1);
            *(u64*)(VH + sr * 144 + c4 * 8) = ((u64)h1 << 32) | h0;
            *(u64*)(VL + sr * 144 + c4 * 8) = ((u64)l1 << 32) | l0_;
        }
        __syncthreads();

        if (tile + 1 < 4) {
#pragma unroll
            for (int j = 0; j < 4; ++j) {
                size_t row = (size_t)(n * Ss + s0 + (tile + 1) * 64 + rbase + 16 * j);
                bk[j] = *(const float4*)(keys   + row * ROWSTRIDE + h * Dd + c4 * 4);
                bv[j] = *(const float4*)(values + row * ROWSTRIDE + h * Dd + c4 * 4);
            }
        }

        const uint32_t KHu = smb + P1_KH + b * 9216;
        const uint32_t KLu = smb + P1_KL + b * 9216;
        const uint32_t VHu = smb + P1_VH + b * 9216;
        const uint32_t VLu = smb + P1_VL + b * 9216;
#pragma unroll
        for (int k2 = 0; k2 < 2; ++k2) {
            const int kt = ki * 2 + k2;
            uint32_t ah[2][4], al[2][4];
#pragma unroll
            for (int m2 = 0; m2 < 2; ++m2) {
                const int mt = mi * 2 + m2;   // e-tile
                ldm4t(ah[m2], VHu + (uint32_t)(kt * 2304 + mt * 32) + aoff);
                ldm4t(al[m2], VLu + (uint32_t)(kt * 2304 + mt * 32) + aoff);
            }
#pragma unroll
            for (int g2 = 0; g2 < 4; ++g2) {
                const int gx = ni * 4 + g2;   // d-group: FULL 0..7 coverage
                uint32_t bh[2], bl[2];
                ldm2t(bh, KHu + (uint32_t)(kt * 2304 + gx * 16) + boff);
                ldm2t(bl, KLu + (uint32_t)(kt * 2304 + gx * 16) + boff);
#pragma unroll
                for (int m2 = 0; m2 < 2; ++m2) {
                    mma_bf16(acc[m2][g2], ah[m2], bh[0], bh[1]);
                    mma_bf16(acc[m2][g2], ah[m2], bl[0], bl[1]);
                    mma_bf16(acc[m2][g2], al[m2], bh[0], bh[1]);
                }
            }
        }
        // next store targets the other buffer; next-iteration sync protects reuse
    }

    // ---- combine k-split pairs via smem; Ksum tree (dead-buffer scratch) ----
    __syncthreads();
    float* S    = (float*)(sm1 + P1_KH);      // 16 KB combine scratch
    float* scrK = (float*)(sm1 + P1_VH);      // 16x68 ksum scratch
    if (ki == 1) {
        const int j = wid >> 1;               // pair id 0..3
#pragma unroll
        for (int m2 = 0; m2 < 2; ++m2)
#pragma unroll
            for (int g2 = 0; g2 < 4; ++g2) {
                const int cell = m2 * 4 + g2; // 0..7
                *(float4*)(S + ((cell * 4 + j) * 32 + lid) * 4) = acc[m2][g2];
            }
    }
    *(float4*)(scrK + rbase * 68 + c4 * 4) = ksum4;
    __syncthreads();

    if (t < 64) {
        float s = 0.f;
#pragma unroll
        for (int r = 0; r < 16; ++r) s += scrK[r * 68 + t];
        g_part_ks[(blockIdx.x * NH + nh) * 64 + t] = s;
    }
    if (ki == 0) {
        const int j = wid >> 1;
        float* base = g_part_kv + ((size_t)blockIdx.x * NH + nh) * 4096;
#pragma unroll
        for (int m2 = 0; m2 < 2; ++m2)
#pragma unroll
            for (int g2 = 0; g2 < 4; ++g2) {
                const int cell = m2 * 4 + g2;
                float4 o = *(float4*)(S + ((cell * 4 + j) * 32 + lid) * 4);
                o.x += acc[m2][g2].x; o.y += acc[m2][g2].y;
                o.z += acc[m2][g2].z; o.w += acc[m2][g2].w;
                const int e0 = (mi * 2 + m2) * 16 + qg;
                const int d0 = (ni * 4 + g2) * 8 + tg * 2;
                *(float2*)(base + e0 * 64 + d0)       = make_float2(o.x, o.y);
                *(float2*)(base + (e0 + 8) * 64 + d0) = make_float2(o.z, o.w);
            }
    }
}

// ============================================================================
// Phase 1b: fixed-order reduction (32 slots)
// ============================================================================
__global__ void reduce_kernel() {
    int i = blockIdx.x * 256 + threadIdx.x;
    if (i < NH * 1024) {
        float4 s = make_float4(0.f, 0.f, 0.f, 0.f);
#pragma unroll
        for (int c = 0; c < P1_CHUNKS; c++) {
            float4 p = *(const float4*)(g_part_kv + (size_t)c * NH * 4096 + i * 4);
            s.x += p.x; s.y += p.y; s.z += p.z; s.w += p.w;
        }
        *(float4*)(g_kv + i * 4) = s;
    } else if (i < NH * 1024 + NH * 16) {
        int j = i - NH * 1024;
        float4 s = make_float4(0.f, 0.f, 0.f, 0.f);
#pragma unroll
        for (int c = 0; c < P1_CHUNKS; c++) {
            float4 p = *(const float4*)(g_part_ks + c * NH * 64 + j * 4);
            s.x += p.x; s.y += p.y; s.z += p.z; s.w += p.w;
        }
        *(float4*)(g_ks + j * 4) = s;
    }
}

// ---- p2 smem: Q hi/lo double-buffered + B(64x144) hi/lo + z scratch ----
constexpr uint32_t P2_QH = 0;           // 2 x 128x144
constexpr uint32_t P2_QL = 36864;
constexpr uint32_t P2_BH = 73728;       // 64x144
constexpr uint32_t P2_BL = 82944;
constexpr uint32_t P2_ZS = 92160;       // 2 x 128 floats
constexpr uint32_t P2_DSM = 93184;

// ============================================================================
// Phase 2: out = (phiQ @ KV) * Z. 256 thr / 8 warps, warp = one m16 l-tile,
// 8 n-tiles (direct-LDS fragments, R7-validated). Z scalar-side. 2 l-tiles
// per CTA, Q double-buffered + register prefetch. Grid (Ll/256, NH).
// ============================================================================
__global__ __launch_bounds__(256) void p2_kernel(const float* __restrict__ queries,
                                                 float* __restrict__ out) {
    extern __shared__ __align__(16) char sm2[];
    char* BH = sm2 + P2_BH; char* BL = sm2 + P2_BL;

    const int t    = threadIdx.x;
    const int wid  = t >> 5, lane = t & 31;
    const int g    = lane >> 2, tg = lane & 3;
    const int nh   = blockIdx.y;
    const int n    = nh >> 3, h = nh & 7;
    const int lbase = blockIdx.x * 256;

    // stage B = KV[e][d] rows (n = e, k = d), direct-LDS consumption
    if (t < 64) {
        const float* src = g_kv + (size_t)nh * 4096 + t * 64;
#pragma unroll
        for (int c = 0; c < 16; ++c) {
            float4 v = *(const float4*)(src + c * 4);
            unsigned hxy, lxy, hzw, lzw;
            bsplit2(v.x, v.y, hxy, lxy);
            bsplit2(v.z, v.w, hzw, lzw);
            *(u64*)(BH + t * 144 + c * 8) = ((u64)hzw << 32) | hxy;
            *(u64*)(BL + t * 144 + c * 8) = ((u64)lzw << 32) | lxy;
        }
    }

    const int c4 = t & 15, rbase = t >> 4;
    const float4 ks4 = *(const float4*)(g_ks + nh * 64 + c4 * 4);

    float4 bq[8];
#pragma unroll
    for (int k2 = 0; k2 < 8; ++k2) {
        size_t row = (size_t)(n * Ll + lbase + rbase + 16 * k2);
        bq[k2] = *(const float4*)(queries + row * ROWSTRIDE + h * Dd + c4 * 4);
    }

    for (int tile = 0; tile < 2; ++tile) {
        char* QH = sm2 + P2_QH + tile * 18432;
        char* QL = sm2 + P2_QL + tile * 18432;
        float* zst = (float*)(sm2 + P2_ZS) + tile * 128;
#pragma unroll
        for (int k2 = 0; k2 < 8; ++k2) {
            const int lr = rbase + 16 * k2;
            unsigned hxy, lxy, hzw, lzw;
            float fx = featmap(bq[k2].x), fy = featmap(bq[k2].y);
            float fz = featmap(bq[k2].z), fw = featmap(bq[k2].w);
            float pz = fx * ks4.x + fy * ks4.y + fz * ks4.z + fw * ks4.w;
            pz += __shfl_xor_sync(0xFFFFFFFFu, pz, 1);
            pz += __shfl_xor_sync(0xFFFFFFFFu, pz, 2);
            pz += __shfl_xor_sync(0xFFFFFFFFu, pz, 4);
            pz += __shfl_xor_sync(0xFFFFFFFFu, pz, 8);
            if (c4 == 0) zst[lr] = pz;
            bsplit2(fx, fy, hxy, lxy);
            bsplit2(fz, fw, hzw, lzw);
            *(u64*)(QH + lr * 144 + c4 * 8) = ((u64)hzw << 32) | hxy;
            *(u64*)(QL + lr * 144 + c4 * 8) = ((u64)lzw << 32) | lxy;
        }
        __syncthreads();

        if (tile == 0) {
#pragma unroll
            for (int k2 = 0; k2 < 8; ++k2) {
                size_t row = (size_t)(n * Ll + lbase + 128 + rbase + 16 * k2);
                bq[k2] = *(const float4*)(queries + row * ROWSTRIDE + h * Dd + c4 * 4);
            }
        }

        float4 C[8];
#pragma unroll
        for (int nt = 0; nt < 8; ++nt) C[nt] = make_float4(0.f, 0.f, 0.f, 0.f);

        const int cb = tg * 4;
#pragma unroll
        for (int kt = 0; kt < 4; ++kt) {
            const int kb = kt * 32 + cb;
            const int r0 = wid * 16 + g;
            uint32_t ah[4], al[4];
            ah[0] = *(const uint32_t*)(QH + r0 * 144 + kb);
            ah[1] = *(const uint32_t*)(QH + (r0 + 8) * 144 + kb);
            ah[2] = *(const uint32_t*)(QH + r0 * 144 + kb + 16);
            ah[3] = *(const uint32_t*)(QH + (r0 + 8) * 144 + kb + 16);
            al[0] = *(const uint32_t*)(QL + r0 * 144 + kb);
            al[1] = *(const uint32_t*)(QL + (r0 + 8) * 144 + kb);
            al[2] = *(const uint32_t*)(QL + r0 * 144 + kb + 16);
            al[3] = *(const uint32_t*)(QL + (r0 + 8) * 144 + kb + 16);
#pragma unroll
            for (int nt = 0; nt < 8; ++nt) {
                const int e0 = nt * 8 + g;
                uint32_t bh0 = *(const uint32_t*)(BH + e0 * 144 + kb);
                uint32_t bh1 = *(const uint32_t*)(BH + e0 * 144 + kb + 16);
                uint32_t bl0 = *(const uint32_t*)(BL + e0 * 144 + kb);
                uint32_t bl1 = *(const uint32_t*)(BL + e0 * 144 + kb + 16);
                mma_bf16(C[nt], ah, bh0, bh1);
                mma_bf16(C[nt], ah, bl0, bl1);
                mma_bf16(C[nt], al, bh0, bh1);
            }
        }

        // epilogue: scale by 1/(z+eps), z from scalar-side scratch
        const int rl = wid * 16 + g;
        float i0 = 1.0f / (zst[rl] + 1e-6f);
        float i1 = 1.0f / (zst[rl + 8] + 1e-6f);
        const int row = lbase + tile * 128 + rl;
        float* p0 = out + ((size_t)(n * Ll + row) * Hh + h) * Dd;
        float* p1 = p0 + (size_t)8 * ROWSTRIDE;
#pragma unroll
        for (int nt = 0; nt < 8; ++nt) {
            const int col = nt * 8 + tg * 2;
            *(float2*)(p0 + col) = make_float2(C[nt].x * i0, C[nt].y * i0);
            *(float2*)(p1 + col) = make_float2(C[nt].z * i1, C[nt].w * i1);
        }
        // next iteration stores to the other Q buffer / zst slot
    }
}

// ============================================================================
extern "C" void kernel_launch(void* const* d_in, const int* in_sizes, int n_in,
                              void* d_out, int out_size) {
    const float* q = (const float*)d_in[0];
    const float* k = (const float*)d_in[1];
    const float* v = (const float*)d_in[2];
    float* o = (float*)d_out;
    (void)in_sizes; (void)n_in; (void)out_size;

    cudaFuncSetAttribute(p1_kernel, cudaFuncAttributeMaxDynamicSharedMemorySize, P1_DSM);
    cudaFuncSetAttribute(p2_kernel, cudaFuncAttributeMaxDynamicSharedMemorySize, P2_DSM);

    p1_kernel<<<dim3(P1_CHUNKS, NH), 256, P1_DSM>>>(k, v);
    reduce_kernel<<<(NH * 1024 + NH * 16 + 255) / 256, 256>>>();
    p2_kernel<<<dim3(Ll / 256, NH), 256, P2_DSM>>>(q, o);
}

// round 12
// speedup vs baseline: 1.2567x; 1.0639x over previous
#include <cuda_runtime.h>
#include <cuda_bf16.h>
#include <cstdint>

// LinearAttention: out[n,l,h,e] = (phi(Q)@KV) * Z, phi = elu+1 (vlen cancels)
//   KV = sum_s phi(K)[s,d] * V[s,e] ;  Z = 1/(phi(Q).Ksum + 1e-6)
//
// R12: p1 = R11 (measured 40.6us) with 512-s chunks (halved partial traffic).
//      p2 = R7's Z-in-GEMM design (measured 42.4us; R11's scalar-Z shfl tree
//      was the p2 regression) reading B from g_kv[e][d] + g_ks row 64.

#define DEV_INLINE __device__ __forceinline__

constexpr int Hh = 8, Dd = 64, Ll = 8192, Ss = 8192, Nn = 4;
constexpr int NH = Nn * Hh;                // 32
constexpr int ROWSTRIDE = Hh * Dd;         // 512
constexpr int P1_CHUNKS = 16;
constexpr int P1_SCHUNK = Ss / P1_CHUNKS;  // 512 s per CTA (8 tiles of 64)
constexpr int P1_NT = P1_SCHUNK / 64;      // 8

__device__ __align__(16) float g_part_kv[(size_t)P1_CHUNKS * NH * 4096]; // [e][d]
__device__ __align__(16) float g_part_ks[P1_CHUNKS * NH * 64];
__device__ __align__(16) float g_kv[NH * 4096];   // [nh][e][d]
__device__ __align__(16) float g_ks[NH * 64];

using u64 = unsigned long long;

DEV_INLINE float featmap(float x) { return __expf(fminf(x, 0.f)) + fmaxf(x, 0.f); }
DEV_INLINE unsigned bf2u(__nv_bfloat162 v) { return *reinterpret_cast<unsigned*>(&v); }
DEV_INLINE void bsplit2(float a, float b, unsigned& h, unsigned& l) {
    __nv_bfloat162 hv = __floats2bfloat162_rn(a, b);
    float2 hf = __bfloat1622float2(hv);
    __nv_bfloat162 lv = __floats2bfloat162_rn(a - hf.x, b - hf.y);
    h = bf2u(hv); l = bf2u(lv);
}
DEV_INLINE uint32_t smem_u32(const void* p) {
    uint32_t a;
    asm("{ .reg .u64 t; cvta.to.shared.u64 t, %1; cvt.u32.u64 %0, t; }"
        : "=r"(a) : "l"(p));
    return a;
}
DEV_INLINE void mma_bf16(float4& c, const uint32_t a[4], uint32_t b0, uint32_t b1) {
    asm volatile(
        "mma.sync.aligned.m16n8k16.row.col.f32.bf16.bf16.f32 "
        "{%0,%1,%2,%3}, {%4,%5,%6,%7}, {%8,%9}, {%0,%1,%2,%3};"
        : "+f"(c.x), "+f"(c.y), "+f"(c.z), "+f"(c.w)
        : "r"(a[0]), "r"(a[1]), "r"(a[2]), "r"(a[3]), "r"(b0), "r"(b1));
}
DEV_INLINE void ldm4t(uint32_t* r, uint32_t addr) {
    asm volatile(
        "ldmatrix.sync.aligned.m8n8.x4.trans.shared.b16 {%0,%1,%2,%3}, [%4];"
        : "=r"(r[0]), "=r"(r[1]), "=r"(r[2]), "=r"(r[3]) : "r"(addr));
}
DEV_INLINE void ldm2t(uint32_t* r, uint32_t addr) {
    asm volatile(
        "ldmatrix.sync.aligned.m8n8.x2.trans.shared.b16 {%0,%1}, [%2];"
        : "=r"(r[0]), "=r"(r[1]) : "r"(addr));
}

// ---- p1 smem: K/V hi/lo, each 2buf x 64 x 144B ----
constexpr uint32_t P1_KH = 0;
constexpr uint32_t P1_KL = 18432;
constexpr uint32_t P1_VH = 36864;
constexpr uint32_t P1_VL = 55296;
constexpr uint32_t P1_DSM = 73728;

// ============================================================================
// Phase 1: D[e][d] = V^T @ phiK. 256 thr / 8 warps. (R11-validated)
// wid: ki=wid&1 (kt pair), ni=(wid>>1)&1, mi=wid>>2. Cells: 2m x 4g.
// k-split pairs combined in-CTA. Grid (P1_CHUNKS, NH).
// ============================================================================
__global__ __launch_bounds__(256) void p1_kernel(const float* __restrict__ keys,
                                                 const float* __restrict__ values) {
    extern __shared__ __align__(16) char sm1[];

    const int t   = threadIdx.x;
    const int wid = t >> 5, lid = t & 31;
    const int grp = lid >> 3, r8 = lid & 7;
    const int qg  = lid >> 2, tg = lid & 3;
    const int nh  = blockIdx.y;
    const int n   = nh >> 3, h = nh & 7;
    const int s0  = blockIdx.x * P1_SCHUNK;
    const int ki  = wid & 1, ni = (wid >> 1) & 1, mi = wid >> 2;

    const uint32_t smb = smem_u32(sm1);
    const uint32_t aoff = (uint32_t)((r8 + ((grp & 2) ? 8 : 0)) * 144 +
                                     ((grp & 1) ? 8 : 0) * 2);
    const uint32_t boff = (uint32_t)((r8 + ((grp & 1) ? 8 : 0)) * 144);

    float4 acc[2][4];
#pragma unroll
    for (int i = 0; i < 2; i++)
#pragma unroll
        for (int j = 0; j < 4; j++) acc[i][j] = make_float4(0.f, 0.f, 0.f, 0.f);
    float4 ksum4 = make_float4(0.f, 0.f, 0.f, 0.f);

    const int c4 = t & 15, rbase = t >> 4;

    float4 bk[4], bv[4];
#pragma unroll
    for (int j = 0; j < 4; ++j) {
        size_t row = (size_t)(n * Ss + s0 + rbase + 16 * j);
        bk[j] = *(const float4*)(keys   + row * ROWSTRIDE + h * Dd + c4 * 4);
        bv[j] = *(const float4*)(values + row * ROWSTRIDE + h * Dd + c4 * 4);
    }

    for (int tile = 0; tile < P1_NT; ++tile) {
        const int b = tile & 1;
        char* KH = sm1 + P1_KH + b * 9216;
        char* KL = sm1 + P1_KL + b * 9216;
        char* VH = sm1 + P1_VH + b * 9216;
        char* VL = sm1 + P1_VL + b * 9216;
#pragma unroll
        for (int j = 0; j < 4; ++j) {
            const int sr = rbase + 16 * j;
            unsigned h0, l0_, h1, l1;
            float fx = featmap(bk[j].x), fy = featmap(bk[j].y);
            float fz = featmap(bk[j].z), fw = featmap(bk[j].w);
            ksum4.x += fx; ksum4.y += fy; ksum4.z += fz; ksum4.w += fw;
            bsplit2(fx, fy, h0, l0_);
            bsplit2(fz, fw, h1, l1);
            *(u64*)(KH + sr * 144 + c4 * 8) = ((u64)h1 << 32) | h0;
            *(u64*)(KL + sr * 144 + c4 * 8) = ((u64)l1 << 32) | l0_;
            bsplit2(bv[j].x, bv[j].y, h0, l0_);
            bsplit2(bv[j].z, bv[j].w, h1, l1);
            *(u64*)(VH + sr * 144 + c4 * 8) = ((u64)h1 << 32) | h0;
            *(u64*)(VL + sr * 144 + c4 * 8) = ((u64)l1 << 32) | l0_;
        }
        __syncthreads();

        if (tile + 1 < P1_NT) {
#pragma unroll
            for (int j = 0; j < 4; ++j) {
                size_t row = (size_t)(n * Ss + s0 + (tile + 1) * 64 + rbase + 16 * j);
                bk[j] = *(const float4*)(keys   + row * ROWSTRIDE + h * Dd + c4 * 4);
                bv[j] = *(const float4*)(values + row * ROWSTRIDE + h * Dd + c4 * 4);
            }
        }

        const uint32_t KHu = smb + P1_KH + b * 9216;
        const uint32_t KLu = smb + P1_KL + b * 9216;
        const uint32_t VHu = smb + P1_VH + b * 9216;
        const uint32_t VLu = smb + P1_VL + b * 9216;
#pragma unroll
        for (int k2 = 0; k2 < 2; ++k2) {
            const int kt = ki * 2 + k2;
            uint32_t ah[2][4], al[2][4];
#pragma unroll
            for (int m2 = 0; m2 < 2; ++m2) {
                const int mt = mi * 2 + m2;   // e-tile
                ldm4t(ah[m2], VHu + (uint32_t)(kt * 2304 + mt * 32) + aoff);
                ldm4t(al[m2], VLu + (uint32_t)(kt * 2304 + mt * 32) + aoff);
            }
#pragma unroll
            for (int g2 = 0; g2 < 4; ++g2) {
                const int gx = ni * 4 + g2;   // d-group (full coverage)
                uint32_t bh[2], bl[2];
                ldm2t(bh, KHu + (uint32_t)(kt * 2304 + gx * 16) + boff);
                ldm2t(bl, KLu + (uint32_t)(kt * 2304 + gx * 16) + boff);
#pragma unroll
                for (int m2 = 0; m2 < 2; ++m2) {
                    mma_bf16(acc[m2][g2], ah[m2], bh[0], bh[1]);
                    mma_bf16(acc[m2][g2], ah[m2], bl[0], bl[1]);
                    mma_bf16(acc[m2][g2], al[m2], bh[0], bh[1]);
                }
            }
        }
    }

    // ---- combine k-split pairs via smem; Ksum tree (dead-buffer scratch) ----
    __syncthreads();
    float* S    = (float*)(sm1 + P1_KH);      // 16 KB combine scratch
    float* scrK = (float*)(sm1 + P1_VH);      // 16x68 ksum scratch
    if (ki == 1) {
        const int j = wid >> 1;
#pragma unroll
        for (int m2 = 0; m2 < 2; ++m2)
#pragma unroll
            for (int g2 = 0; g2 < 4; ++g2) {
                const int cell = m2 * 4 + g2;
                *(float4*)(S + ((cell * 4 + j) * 32 + lid) * 4) = acc[m2][g2];
            }
    }
    *(float4*)(scrK + rbase * 68 + c4 * 4) = ksum4;
    __syncthreads();

    if (t < 64) {
        float s = 0.f;
#pragma unroll
        for (int r = 0; r < 16; ++r) s += scrK[r * 68 + t];
        g_part_ks[(blockIdx.x * NH + nh) * 64 + t] = s;
    }
    if (ki == 0) {
        const int j = wid >> 1;
        float* base = g_part_kv + ((size_t)blockIdx.x * NH + nh) * 4096;
#pragma unroll
        for (int m2 = 0; m2 < 2; ++m2)
#pragma unroll
            for (int g2 = 0; g2 < 4; ++g2) {
                const int cell = m2 * 4 + g2;
                float4 o = *(float4*)(S + ((cell * 4 + j) * 32 + lid) * 4);
                o.x += acc[m2][g2].x; o.y += acc[m2][g2].y;
                o.z += acc[m2][g2].z; o.w += acc[m2][g2].w;
                const int e0 = (mi * 2 + m2) * 16 + qg;
                const int d0 = (ni * 4 + g2) * 8 + tg * 2;
                *(float2*)(base + e0 * 64 + d0)       = make_float2(o.x, o.y);
                *(float2*)(base + (e0 + 8) * 64 + d0) = make_float2(o.z, o.w);
            }
    }
}

// ============================================================================
// Phase 1b: fixed-order reduction (16 slots)
// ============================================================================
__global__ void reduce_kernel() {
    int i = blockIdx.x * 256 + threadIdx.x;
    if (i < NH * 1024) {
        float4 s = make_float4(0.f, 0.f, 0.f, 0.f);
#pragma unroll
        for (int c = 0; c < P1_CHUNKS; c++) {
            float4 p = *(const float4*)(g_part_kv + (size_t)c * NH * 4096 + i * 4);
            s.x += p.x; s.y += p.y; s.z += p.z; s.w += p.w;
        }
        *(float4*)(g_kv + i * 4) = s;
    } else if (i < NH * 1024 + NH * 16) {
        int j = i - NH * 1024;
        float4 s = make_float4(0.f, 0.f, 0.f, 0.f);
#pragma unroll
        for (int c = 0; c < P1_CHUNKS; c++) {
            float4 p = *(const float4*)(g_part_ks + c * NH * 64 + j * 4);
            s.x += p.x; s.y += p.y; s.z += p.z; s.w += p.w;
        }
        *(float4*)(g_ks + j * 4) = s;
    }
}

// ---- p2 smem: Q hi/lo double-buffered + B(72x144) hi/lo ----
constexpr uint32_t P2_QH = 0;           // 2 x 128x144
constexpr uint32_t P2_QL = 36864;
constexpr uint32_t P2_BH = 73728;       // 72x144
constexpr uint32_t P2_BL = 84096;
constexpr uint32_t P2_DSM = 94464;

// ============================================================================
// Phase 2 (R7-validated): out = (phiQ @ KV_ext) * Z. 256 thr / 8 warps,
// warp = one m16 l-tile, 9 n-tiles (Z = B row 64 = Ksum). 2 l-tiles per CTA,
// Q double-buffered + register prefetch. Grid (Ll/256, NH).
// ============================================================================
__global__ __launch_bounds__(256) void p2_kernel(const float* __restrict__ queries,
                                                 float* __restrict__ out) {
    extern __shared__ __align__(16) char sm2[];
    char* BH = sm2 + P2_BH; char* BL = sm2 + P2_BL;

    const int t    = threadIdx.x;
    const int wid  = t >> 5, lane = t & 31;
    const int g    = lane >> 2, tg = lane & 3;
    const int nh   = blockIdx.y;
    const int n    = nh >> 3, h = nh & 7;
    const int lbase = blockIdx.x * 256;

    // stage B: rows 0..63 = g_kv[e][d], row 64 = g_ks (Ksum), 65..71 = 0
    if (t < 72) {
        const float* src = (t < 64) ? (g_kv + (size_t)nh * 4096 + t * 64)
                                    : (g_ks + nh * 64);
#pragma unroll
        for (int c = 0; c < 16; ++c) {
            float4 v = (t <= 64) ? *(const float4*)(src + c * 4)
                                 : make_float4(0.f, 0.f, 0.f, 0.f);
            unsigned hxy, lxy, hzw, lzw;
            bsplit2(v.x, v.y, hxy, lxy);
            bsplit2(v.z, v.w, hzw, lzw);
            *(u64*)(BH + t * 144 + c * 8) = ((u64)hzw << 32) | hxy;
            *(u64*)(BL + t * 144 + c * 8) = ((u64)lzw << 32) | lxy;
        }
    }

    const int c4 = t & 15, rbase = t >> 4;

    float4 bq[8];
#pragma unroll
    for (int k2 = 0; k2 < 8; ++k2) {
        size_t row = (size_t)(n * Ll + lbase + rbase + 16 * k2);
        bq[k2] = *(const float4*)(queries + row * ROWSTRIDE + h * Dd + c4 * 4);
    }

    for (int tile = 0; tile < 2; ++tile) {
        char* QH = sm2 + P2_QH + tile * 18432;
        char* QL = sm2 + P2_QL + tile * 18432;
#pragma unroll
        for (int k2 = 0; k2 < 8; ++k2) {
            const int lr = rbase + 16 * k2;
            unsigned hxy, lxy, hzw, lzw;
            float fx = featmap(bq[k2].x), fy = featmap(bq[k2].y);
            float fz = featmap(bq[k2].z), fw = featmap(bq[k2].w);
            bsplit2(fx, fy, hxy, lxy);
            bsplit2(fz, fw, hzw, lzw);
            *(u64*)(QH + lr * 144 + c4 * 8) = ((u64)hzw << 32) | hxy;
            *(u64*)(QL + lr * 144 + c4 * 8) = ((u64)lzw << 32) | lxy;
        }
        __syncthreads();

        if (tile == 0) {
#pragma unroll
            for (int k2 = 0; k2 < 8; ++k2) {
                size_t row = (size_t)(n * Ll + lbase + 128 + rbase + 16 * k2);
                bq[k2] = *(const float4*)(queries + row * ROWSTRIDE + h * Dd + c4 * 4);
            }
        }

        float4 C[9];
#pragma unroll
        for (int nt = 0; nt < 9; ++nt) C[nt] = make_float4(0.f, 0.f, 0.f, 0.f);

        const int cb = tg * 4;
#pragma unroll
        for (int kt = 0; kt < 4; ++kt) {
            const int kb = kt * 32 + cb;
            const int r0 = wid * 16 + g;
            uint32_t ah[4], al[4];
            ah[0] = *(const uint32_t*)(QH + r0 * 144 + kb);
            ah[1] = *(const uint32_t*)(QH + (r0 + 8) * 144 + kb);
            ah[2] = *(const uint32_t*)(QH + r0 * 144 + kb + 16);
            ah[3] = *(const uint32_t*)(QH + (r0 + 8) * 144 + kb + 16);
            al[0] = *(const uint32_t*)(QL + r0 * 144 + kb);
            al[1] = *(const uint32_t*)(QL + (r0 + 8) * 144 + kb);
            al[2] = *(const uint32_t*)(QL + r0 * 144 + kb + 16);
            al[3] = *(const uint32_t*)(QL + (r0 + 8) * 144 + kb + 16);
#pragma unroll
            for (int nt = 0; nt < 9; ++nt) {
                const int e0 = nt * 8 + g;
                uint32_t bh0 = *(const uint32_t*)(BH + e0 * 144 + kb);
                uint32_t bh1 = *(const uint32_t*)(BH + e0 * 144 + kb + 16);
                uint32_t bl0 = *(const uint32_t*)(BL + e0 * 144 + kb);
                uint32_t bl1 = *(const uint32_t*)(BL + e0 * 144 + kb + 16);
                mma_bf16(C[nt], ah, bh0, bh1);
                mma_bf16(C[nt], ah, bl0, bl1);
                mma_bf16(C[nt], al, bh0, bh1);
            }
        }

        // epilogue: Z = C[8] col 0 (quad-leader lanes), 2 shfls total
        const int src = (lane >> 2) << 2;
        float z0 = __shfl_sync(0xFFFFFFFFu, C[8].x, src);
        float z1 = __shfl_sync(0xFFFFFFFFu, C[8].z, src);
        float i0 = 1.0f / (z0 + 1e-6f);
        float i1 = 1.0f / (z1 + 1e-6f);
        const int row = lbase + tile * 128 + wid * 16 + g;
        float* p0 = out + ((size_t)(n * Ll + row) * Hh + h) * Dd;
        float* p1 = p0 + (size_t)8 * ROWSTRIDE;
#pragma unroll
        for (int nt = 0; nt < 8; ++nt) {
            const int col = nt * 8 + tg * 2;
            *(float2*)(p0 + col) = make_float2(C[nt].x * i0, C[nt].y * i0);
            *(float2*)(p1 + col) = make_float2(C[nt].z * i1, C[nt].w * i1);
        }
        // next iteration stores to the other Q buffer
    }
}

// ============================================================================
extern "C" void kernel_launch(void* const* d_in, const int* in_sizes, int n_in,
                              void* d_out, int out_size) {
    const float* q = (const float*)d_in[0];
    const float* k = (const float*)d_in[1];
    const float* v = (const float*)d_in[2];
    float* o = (float*)d_out;
    (void)in_sizes; (void)n_in; (void)out_size;

    cudaFuncSetAttribute(p1_kernel, cudaFuncAttributeMaxDynamicSharedMemorySize, P1_DSM);
    cudaFuncSetAttribute(p2_kernel, cudaFuncAttributeMaxDynamicSharedMemorySize, P2_DSM);

    p1_kernel<<<dim3(P1_CHUNKS, NH), 256, P1_DSM>>>(k, v);
    reduce_kernel<<<(NH * 1024 + NH * 16 + 255) / 256, 256>>>();
    p2_kernel<<<dim3(Ll / 256, NH), 256, P2_DSM>>>(q, o);
}

// round 13
// speedup vs baseline: 1.2656x; 1.0071x over previous
#include <cuda_runtime.h>
#include <cuda_bf16.h>
#include <cstdint>

// LinearAttention: out[n,l,h,e] = (phi(Q)@KV) * Z, phi = elu+1 (vlen cancels)
//   KV = sum_s phi(K)[s,d] * V[s,e] ;  Z = 1/(phi(Q).Ksum + 1e-6)
//
// R13: p1 + reduce = R12 (measured 39.1 + ~3 us). p2 rebuilt register-direct:
// A-fragments loaded as coalesced float2 straight from gmem Q (layout matches
// the m16n8k16 A fragment exactly), featmap+split in registers, NO Q smem and
// NO per-tile syncs. B = KV_ext[e][d] + Ksum row staged once (Z-in-GEMM).

#define DEV_INLINE __device__ __forceinline__

constexpr int Hh = 8, Dd = 64, Ll = 8192, Ss = 8192, Nn = 4;
constexpr int NH = Nn * Hh;                // 32
constexpr int ROWSTRIDE = Hh * Dd;         // 512
constexpr int P1_CHUNKS = 16;
constexpr int P1_SCHUNK = Ss / P1_CHUNKS;  // 512 s per CTA (8 tiles of 64)
constexpr int P1_NT = P1_SCHUNK / 64;      // 8

__device__ __align__(16) float g_part_kv[(size_t)P1_CHUNKS * NH * 4096]; // [e][d]
__device__ __align__(16) float g_part_ks[P1_CHUNKS * NH * 64];
__device__ __align__(16) float g_kv[NH * 4096];   // [nh][e][d]
__device__ __align__(16) float g_ks[NH * 64];

using u64 = unsigned long long;

DEV_INLINE float featmap(float x) { return __expf(fminf(x, 0.f)) + fmaxf(x, 0.f); }
DEV_INLINE unsigned bf2u(__nv_bfloat162 v) { return *reinterpret_cast<unsigned*>(&v); }
DEV_INLINE void bsplit2(float a, float b, unsigned& h, unsigned& l) {
    __nv_bfloat162 hv = __floats2bfloat162_rn(a, b);
    float2 hf = __bfloat1622float2(hv);
    __nv_bfloat162 lv = __floats2bfloat162_rn(a - hf.x, b - hf.y);
    h = bf2u(hv); l = bf2u(lv);
}
DEV_INLINE uint32_t smem_u32(const void* p) {
    uint32_t a;
    asm("{ .reg .u64 t; cvta.to.shared.u64 t, %1; cvt.u32.u64 %0, t; }"
        : "=r"(a) : "l"(p));
    return a;
}
DEV_INLINE void mma_bf16(float4& c, const uint32_t a[4], uint32_t b0, uint32_t b1) {
    asm volatile(
        "mma.sync.aligned.m16n8k16.row.col.f32.bf16.bf16.f32 "
        "{%0,%1,%2,%3}, {%4,%5,%6,%7}, {%8,%9}, {%0,%1,%2,%3};"
        : "+f"(c.x), "+f"(c.y), "+f"(c.z), "+f"(c.w)
        : "r"(a[0]), "r"(a[1]), "r"(a[2]), "r"(a[3]), "r"(b0), "r"(b1));
}
DEV_INLINE void ldm4t(uint32_t* r, uint32_t addr) {
    asm volatile(
        "ldmatrix.sync.aligned.m8n8.x4.trans.shared.b16 {%0,%1,%2,%3}, [%4];"
        : "=r"(r[0]), "=r"(r[1]), "=r"(r[2]), "=r"(r[3]) : "r"(addr));
}
DEV_INLINE void ldm2t(uint32_t* r, uint32_t addr) {
    asm volatile(
        "ldmatrix.sync.aligned.m8n8.x2.trans.shared.b16 {%0,%1}, [%2];"
        : "=r"(r[0]), "=r"(r[1]) : "r"(addr));
}

// ---- p1 smem: K/V hi/lo, each 2buf x 64 x 144B ----
constexpr uint32_t P1_KH = 0;
constexpr uint32_t P1_KL = 18432;
constexpr uint32_t P1_VH = 36864;
constexpr uint32_t P1_VL = 55296;
constexpr uint32_t P1_DSM = 73728;

// ============================================================================
// Phase 1 (R12-measured 39.1us): D[e][d] = V^T @ phiK. 256 thr / 8 warps.
// wid: ki=wid&1, ni=(wid>>1)&1, mi=wid>>2. Cells: 2m x 4g. Grid (16, NH).
// ============================================================================
__global__ __launch_bounds__(256) void p1_kernel(const float* __restrict__ keys,
                                                 const float* __restrict__ values) {
    extern __shared__ __align__(16) char sm1[];

    const int t   = threadIdx.x;
    const int wid = t >> 5, lid = t & 31;
    const int grp = lid >> 3, r8 = lid & 7;
    const int qg  = lid >> 2, tg = lid & 3;
    const int nh  = blockIdx.y;
    const int n   = nh >> 3, h = nh & 7;
    const int s0  = blockIdx.x * P1_SCHUNK;
    const int ki  = wid & 1, ni = (wid >> 1) & 1, mi = wid >> 2;

    const uint32_t smb = smem_u32(sm1);
    const uint32_t aoff = (uint32_t)((r8 + ((grp & 2) ? 8 : 0)) * 144 +
                                     ((grp & 1) ? 8 : 0) * 2);
    const uint32_t boff = (uint32_t)((r8 + ((grp & 1) ? 8 : 0)) * 144);

    float4 acc[2][4];
#pragma unroll
    for (int i = 0; i < 2; i++)
#pragma unroll
        for (int j = 0; j < 4; j++) acc[i][j] = make_float4(0.f, 0.f, 0.f, 0.f);
    float4 ksum4 = make_float4(0.f, 0.f, 0.f, 0.f);

    const int c4 = t & 15, rbase = t >> 4;

    float4 bk[4], bv[4];
#pragma unroll
    for (int j = 0; j < 4; ++j) {
        size_t row = (size_t)(n * Ss + s0 + rbase + 16 * j);
        bk[j] = *(const float4*)(keys   + row * ROWSTRIDE + h * Dd + c4 * 4);
        bv[j] = *(const float4*)(values + row * ROWSTRIDE + h * Dd + c4 * 4);
    }

    for (int tile = 0; tile < P1_NT; ++tile) {
        const int b = tile & 1;
        char* KH = sm1 + P1_KH + b * 9216;
        char* KL = sm1 + P1_KL + b * 9216;
        char* VH = sm1 + P1_VH + b * 9216;
        char* VL = sm1 + P1_VL + b * 9216;
#pragma unroll
        for (int j = 0; j < 4; ++j) {
            const int sr = rbase + 16 * j;
            unsigned h0, l0_, h1, l1;
            float fx = featmap(bk[j].x), fy = featmap(bk[j].y);
            float fz = featmap(bk[j].z), fw = featmap(bk[j].w);
            ksum4.x += fx; ksum4.y += fy; ksum4.z += fz; ksum4.w += fw;
            bsplit2(fx, fy, h0, l0_);
            bsplit2(fz, fw, h1, l1);
            *(u64*)(KH + sr * 144 + c4 * 8) = ((u64)h1 << 32) | h0;
            *(u64*)(KL + sr * 144 + c4 * 8) = ((u64)l1 << 32) | l0_;
            bsplit2(bv[j].x, bv[j].y, h0, l0_);
            bsplit2(bv[j].z, bv[j].w, h1, l1);
            *(u64*)(VH + sr * 144 + c4 * 8) = ((u64)h1 << 32) | h0;
            *(u64*)(VL + sr * 144 + c4 * 8) = ((u64)l1 << 32) | l0_;
        }
        __syncthreads();

        if (tile + 1 < P1_NT) {
#pragma unroll
            for (int j = 0; j < 4; ++j) {
                size_t row = (size_t)(n * Ss + s0 + (tile + 1) * 64 + rbase + 16 * j);
                bk[j] = *(const float4*)(keys   + row * ROWSTRIDE + h * Dd + c4 * 4);
                bv[j] = *(const float4*)(values + row * ROWSTRIDE + h * Dd + c4 * 4);
            }
        }

        const uint32_t KHu = smb + P1_KH + b * 9216;
        const uint32_t KLu = smb + P1_KL + b * 9216;
        const uint32_t VHu = smb + P1_VH + b * 9216;
        const uint32_t VLu = smb + P1_VL + b * 9216;
#pragma unroll
        for (int k2 = 0; k2 < 2; ++k2) {
            const int kt = ki * 2 + k2;
            uint32_t ah[2][4], al[2][4];
#pragma unroll
            for (int m2 = 0; m2 < 2; ++m2) {
                const int mt = mi * 2 + m2;   // e-tile
                ldm4t(ah[m2], VHu + (uint32_t)(kt * 2304 + mt * 32) + aoff);
                ldm4t(al[m2], VLu + (uint32_t)(kt * 2304 + mt * 32) + aoff);
            }
#pragma unroll
            for (int g2 = 0; g2 < 4; ++g2) {
                const int gx = ni * 4 + g2;   // d-group (full coverage)
                uint32_t bh[2], bl[2];
                ldm2t(bh, KHu + (uint32_t)(kt * 2304 + gx * 16) + boff);
                ldm2t(bl, KLu + (uint32_t)(kt * 2304 + gx * 16) + boff);
#pragma unroll
                for (int m2 = 0; m2 < 2; ++m2) {
                    mma_bf16(acc[m2][g2], ah[m2], bh[0], bh[1]);
                    mma_bf16(acc[m2][g2], ah[m2], bl[0], bl[1]);
                    mma_bf16(acc[m2][g2], al[m2], bh[0], bh[1]);
                }
            }
        }
    }

    // ---- combine k-split pairs via smem; Ksum tree (dead-buffer scratch) ----
    __syncthreads();
    float* S    = (float*)(sm1 + P1_KH);      // 16 KB combine scratch
    float* scrK = (float*)(sm1 + P1_VH);      // 16x68 ksum scratch
    if (ki == 1) {
        const int j = wid >> 1;
#pragma unroll
        for (int m2 = 0; m2 < 2; ++m2)
#pragma unroll
            for (int g2 = 0; g2 < 4; ++g2) {
                const int cell = m2 * 4 + g2;
                *(float4*)(S + ((cell * 4 + j) * 32 + lid) * 4) = acc[m2][g2];
            }
    }
    *(float4*)(scrK + rbase * 68 + c4 * 4) = ksum4;
    __syncthreads();

    if (t < 64) {
        float s = 0.f;
#pragma unroll
        for (int r = 0; r < 16; ++r) s += scrK[r * 68 + t];
        g_part_ks[(blockIdx.x * NH + nh) * 64 + t] = s;
    }
    if (ki == 0) {
        const int j = wid >> 1;
        float* base = g_part_kv + ((size_t)blockIdx.x * NH + nh) * 4096;
#pragma unroll
        for (int m2 = 0; m2 < 2; ++m2)
#pragma unroll
            for (int g2 = 0; g2 < 4; ++g2) {
                const int cell = m2 * 4 + g2;
                float4 o = *(float4*)(S + ((cell * 4 + j) * 32 + lid) * 4);
                o.x += acc[m2][g2].x; o.y += acc[m2][g2].y;
                o.z += acc[m2][g2].z; o.w += acc[m2][g2].w;
                const int e0 = (mi * 2 + m2) * 16 + qg;
                const int d0 = (ni * 4 + g2) * 8 + tg * 2;
                *(float2*)(base + e0 * 64 + d0)       = make_float2(o.x, o.y);
                *(float2*)(base + (e0 + 8) * 64 + d0) = make_float2(o.z, o.w);
            }
    }
}

// ============================================================================
// Phase 1b: fixed-order reduction (16 slots)
// ============================================================================
__global__ void reduce_kernel() {
    int i = blockIdx.x * 256 + threadIdx.x;
    if (i < NH * 1024) {
        float4 s = make_float4(0.f, 0.f, 0.f, 0.f);
#pragma unroll
        for (int c = 0; c < P1_CHUNKS; c++) {
            float4 p = *(const float4*)(g_part_kv + (size_t)c * NH * 4096 + i * 4);
            s.x += p.x; s.y += p.y; s.z += p.z; s.w += p.w;
        }
        *(float4*)(g_kv + i * 4) = s;
    } else if (i < NH * 1024 + NH * 16) {
        int j = i - NH * 1024;
        float4 s = make_float4(0.f, 0.f, 0.f, 0.f);
#pragma unroll
        for (int c = 0; c < P1_CHUNKS; c++) {
            float4 p = *(const float4*)(g_part_ks + c * NH * 64 + j * 4);
            s.x += p.x; s.y += p.y; s.z += p.z; s.w += p.w;
        }
        *(float4*)(g_ks + j * 4) = s;
    }
}

// ---- p2 smem: B only (72 x 144B hi/lo) ----
constexpr uint32_t P2_BH = 0;
constexpr uint32_t P2_BL = 10368;
constexpr uint32_t P2_DSM = 20736;

// ============================================================================
// Phase 2: out = (phiQ @ KV_ext) * Z. 256 thr / 8 warps, warp = one m16
// l-tile per tile-iter, 9 n-tiles (Z = B row 64). A-fragments register-direct
// from gmem (coalesced float2, featmap+split in regs). 2 l-tiles per CTA,
// both prefetched. Single sync (B staging). Grid (Ll/256, NH).
// ============================================================================
__global__ __launch_bounds__(256, 2) void p2_kernel(const float* __restrict__ queries,
                                                    float* __restrict__ out) {
    extern __shared__ __align__(16) char sm2[];
    char* BH = sm2 + P2_BH; char* BL = sm2 + P2_BL;

    const int t    = threadIdx.x;
    const int wid  = t >> 5, lane = t & 31;
    const int g    = lane >> 2, tg = lane & 3;
    const int nh   = blockIdx.y;
    const int n    = nh >> 3, h = nh & 7;
    const int lbase = blockIdx.x * 256;

    // stage B: rows 0..63 = g_kv[e][d], row 64 = g_ks (Ksum), 65..71 = 0
    if (t < 72) {
        const float* src = (t < 64) ? (g_kv + (size_t)nh * 4096 + t * 64)
                                    : (g_ks + nh * 64);
#pragma unroll
        for (int c = 0; c < 16; ++c) {
            float4 v = (t <= 64) ? *(const float4*)(src + c * 4)
                                 : make_float4(0.f, 0.f, 0.f, 0.f);
            unsigned hxy, lxy, hzw, lzw;
            bsplit2(v.x, v.y, hxy, lxy);
            bsplit2(v.z, v.w, hzw, lzw);
            *(u64*)(BH + t * 144 + c * 8) = ((u64)hzw << 32) | hxy;
            *(u64*)(BL + t * 144 + c * 8) = ((u64)lzw << 32) | lxy;
        }
    }

    // raw Q fragment loads for BOTH tiles (A-frag layout == coalesced float2)
    // thread needs Q[r][kt*16 + tg*2 (+8)] for r = row0, row0+8
    const int r0 = wid * 16 + g;
    const float* qb = queries + ((size_t)(n * Ll + lbase) * ROWSTRIDE + h * Dd);
    float2 q[2][16];
#pragma unroll
    for (int tile = 0; tile < 2; ++tile) {
        const float* rowp = qb + (size_t)(tile * 128 + r0) * ROWSTRIDE;
#pragma unroll
        for (int kt = 0; kt < 4; ++kt) {
            const int col = kt * 16 + tg * 2;
            q[tile][kt * 4 + 0] = *(const float2*)(rowp + col);
            q[tile][kt * 4 + 1] = *(const float2*)(rowp + 8 * ROWSTRIDE + col);
            q[tile][kt * 4 + 2] = *(const float2*)(rowp + col + 8);
            q[tile][kt * 4 + 3] = *(const float2*)(rowp + 8 * ROWSTRIDE + col + 8);
        }
    }
    __syncthreads();   // B staged

#pragma unroll
    for (int tile = 0; tile < 2; ++tile) {
        float4 C[9];
#pragma unroll
        for (int nt = 0; nt < 9; ++nt) C[nt] = make_float4(0.f, 0.f, 0.f, 0.f);

#pragma unroll
        for (int kt = 0; kt < 4; ++kt) {
            // convert this kt's fragments in registers
            uint32_t ah[4], al[4];
#pragma unroll
            for (int j = 0; j < 4; ++j) {
                float2 v = q[tile][kt * 4 + j];
                bsplit2(featmap(v.x), featmap(v.y), ah[j], al[j]);
            }
            const int kb = kt * 32 + tg * 4;
#pragma unroll
            for (int nt = 0; nt < 9; ++nt) {
                const int e0 = nt * 8 + g;
                uint32_t bh0 = *(const uint32_t*)(BH + e0 * 144 + kb);
                uint32_t bh1 = *(const uint32_t*)(BH + e0 * 144 + kb + 16);
                uint32_t bl0 = *(const uint32_t*)(BL + e0 * 144 + kb);
                uint32_t bl1 = *(const uint32_t*)(BL + e0 * 144 + kb + 16);
                mma_bf16(C[nt], ah, bh0, bh1);
                mma_bf16(C[nt], ah, bl0, bl1);
                mma_bf16(C[nt], al, bh0, bh1);
            }
        }

        // epilogue: Z = C[8] col 0 (quad-leader lanes)
        const int src = (lane >> 2) << 2;
        float z0 = __shfl_sync(0xFFFFFFFFu, C[8].x, src);
        float z1 = __shfl_sync(0xFFFFFFFFu, C[8].z, src);
        float i0 = 1.0f / (z0 + 1e-6f);
        float i1 = 1.0f / (z1 + 1e-6f);
        const int row = lbase + tile * 128 + r0;
        float* p0 = out + ((size_t)(n * Ll + row) * Hh + h) * Dd;
        float* p1 = p0 + (size_t)8 * ROWSTRIDE;
#pragma unroll
        for (int nt = 0; nt < 8; ++nt) {
            const int col = nt * 8 + tg * 2;
            *(float2*)(p0 + col) = make_float2(C[nt].x * i0, C[nt].y * i0);
            *(float2*)(p1 + col) = make_float2(C[nt].z * i1, C[nt].w * i1);
        }
    }
}

// ============================================================================
extern "C" void kernel_launch(void* const* d_in, const int* in_sizes, int n_in,
                              void* d_out, int out_size) {
    const float* q = (const float*)d_in[0];
    const float* k = (const float*)d_in[1];
    const float* v = (const float*)d_in[2];
    float* o = (float*)d_out;
    (void)in_sizes; (void)n_in; (void)out_size;

    cudaFuncSetAttribute(p1_kernel, cudaFuncAttributeMaxDynamicSharedMemorySize, P1_DSM);
    cudaFuncSetAttribute(p2_kernel, cudaFuncAttributeMaxDynamicSharedMemorySize, P2_DSM);

    p1_kernel<<<dim3(P1_CHUNKS, NH), 256, P1_DSM>>>(k, v);
    reduce_kernel<<<(NH * 1024 + NH * 16 + 255) / 256, 256>>>();
    p2_kernel<<<dim3(Ll / 256, NH), 256, P2_DSM>>>(q, o);
}